// round 1
// baseline (speedup 1.0000x reference)
#include <cuda_runtime.h>

#define N_NODES 100000
#define N_EDGES 1600000
#define IN_CH   32
#define HID     128
#define OUT_CH  32

// ---------------- scratch (device globals; no allocation allowed) ----------
__device__ __align__(16) int   g_cnt[N_NODES];
__device__ __align__(16) int   g_off[N_NODES + 1];
__device__ __align__(16) int   g_cur[N_NODES];
__device__ __align__(16) int   g_col[N_EDGES];          // src per dst-sorted edge
__device__ __align__(16) float g_inv[N_NODES];          // 1/max(deg,1)
__device__ __align__(16) float g_agg1[N_NODES * IN_CH]; // unscaled neighbor sum, layer1
__device__ __align__(16) float g_h[N_NODES * HID];      // relu(layer1)
__device__ __align__(16) float g_agg2[N_NODES * HID];   // unscaled neighbor sum, layer2
__device__ int g_is64;                                   // edge_index dtype flag

// ---------------- dtype detection: int64 vs int32 edge_index ---------------
// int64 values < 100000 -> every odd 32-bit word is 0. Random int32 data has
// ~0 probability of 128 consecutive odd words being zero.
__global__ void detect_kernel(const unsigned int* ei32) {
    __shared__ int flag;
    if (threadIdx.x == 0) flag = 0;
    __syncthreads();
    if (ei32[2 * threadIdx.x + 1] != 0u) flag = 1;
    __syncthreads();
    if (threadIdx.x == 0) g_is64 = flag ? 0 : 1;
}

__device__ __forceinline__ int load_idx(const void* ei, long long pos, int is64) {
    if (is64) return (int)((const long long*)ei)[pos];
    return ((const int*)ei)[pos];
}

// ---------------- CSR build ------------------------------------------------
__global__ void zero_cnt_kernel() {
    int i = blockIdx.x * blockDim.x + threadIdx.x;
    if (i < N_NODES) g_cnt[i] = 0;
}

__global__ void hist_kernel(const void* ei) {
    int e = blockIdx.x * blockDim.x + threadIdx.x;
    if (e >= N_EDGES) return;
    int is64 = g_is64;
    int d = load_idx(ei, (long long)N_EDGES + e, is64);
    atomicAdd(&g_cnt[d], 1);
}

// single-block exclusive scan of g_cnt -> g_off (N+1 entries)
__global__ void scan_kernel() {
    __shared__ int sdata[1024];
    __shared__ int carry;
    int tid = threadIdx.x;
    if (tid == 0) carry = 0;
    __syncthreads();
    for (int base = 0; base < N_NODES; base += 1024) {
        int i = base + tid;
        int v = (i < N_NODES) ? g_cnt[i] : 0;
        sdata[tid] = v;
        __syncthreads();
        for (int o = 1; o < 1024; o <<= 1) {
            int t = (tid >= o) ? sdata[tid - o] : 0;
            __syncthreads();
            sdata[tid] += t;
            __syncthreads();
        }
        int incl = sdata[tid];
        int c = carry;
        __syncthreads();
        if (i < N_NODES) g_off[i] = c + incl - v;
        if (tid == 1023) carry = c + incl;
        __syncthreads();
    }
    if (tid == 0) g_off[N_NODES] = carry;
}

__global__ void cursor_inv_kernel() {
    int i = blockIdx.x * blockDim.x + threadIdx.x;
    if (i < N_NODES) {
        g_cur[i] = g_off[i];
        int d = g_cnt[i];
        g_inv[i] = 1.0f / (float)(d > 1 ? d : 1);
    }
}

__global__ void scatter_kernel(const void* ei) {
    int e = blockIdx.x * blockDim.x + threadIdx.x;
    if (e >= N_EDGES) return;
    int is64 = g_is64;
    int s = load_idx(ei, e, is64);
    int d = load_idx(ei, (long long)N_EDGES + e, is64);
    int p = atomicAdd(&g_cur[d], 1);
    g_col[p] = s;
}

// ---------------- aggregation (warp per dst node, gather, no float atomics)
__global__ void agg1_kernel(const float* __restrict__ x) {
    int node = blockIdx.x * 8 + (threadIdx.x >> 5);
    if (node >= N_NODES) return;
    int lane = threadIdx.x & 31;
    int b = g_off[node], e = g_off[node + 1];
    float acc = 0.f;
    for (int i = b; i < e; i++) {
        int s = g_col[i];                       // uniform across warp -> 1 request
        acc += x[s * IN_CH + lane];             // 128B coalesced row
    }
    g_agg1[node * IN_CH + lane] = acc;
}

__global__ void agg2_kernel() {
    int node = blockIdx.x * 8 + (threadIdx.x >> 5);
    if (node >= N_NODES) return;
    int lane = threadIdx.x & 31;
    int b = g_off[node], e = g_off[node + 1];
    const float4* h4 = (const float4*)g_h;
    float4 acc = make_float4(0.f, 0.f, 0.f, 0.f);
    for (int i = b; i < e; i++) {
        int s = g_col[i];
        float4 v = h4[s * 32 + lane];           // 512B coalesced row
        acc.x += v.x; acc.y += v.y; acc.z += v.z; acc.w += v.w;
    }
    ((float4*)g_agg2)[node * 32 + lane] = acc;
}

// ---------------- layer1 GEMM: h = relu(agg1*inv @ W1l^T + x @ W1r^T + b1)
// tile: 64 nodes x 128 outs, 256 threads, each thread 8 nodes x 4 outs.
__global__ void gemm1_kernel(const float* __restrict__ x,
                             const float* __restrict__ W1l,
                             const float* __restrict__ W1r,
                             const float* __restrict__ b1) {
    __shared__ float s_u[32][68];    // [k][node], padded: 16B-aligned rows
    __shared__ float s_w[32][132];   // [k][t]
    int tid = threadIdx.x;
    int node0 = blockIdx.x * 64;
    int t4 = (tid & 31) * 4;
    int n8 = (tid >> 5) * 8;
    float acc[8][4];
#pragma unroll
    for (int n = 0; n < 8; n++)
#pragma unroll
        for (int j = 0; j < 4; j++) acc[n][j] = 0.f;

    for (int c = 0; c < 2; c++) {   // c=0: agg1*inv with W1l ; c=1: x with W1r
        for (int idx = tid; idx < 64 * 32; idx += 256) {
            int n = idx >> 5, kk = idx & 31;
            int gn = node0 + n;
            float v = 0.f;
            if (gn < N_NODES)
                v = c ? x[gn * 32 + kk] : g_agg1[gn * 32 + kk] * g_inv[gn];
            s_u[kk][n] = v;
        }
        for (int idx = tid; idx < 128 * 32; idx += 256) {
            int t = idx >> 5, kk = idx & 31;
            s_w[kk][t] = c ? W1r[t * 32 + kk] : W1l[t * 32 + kk];
        }
        __syncthreads();
#pragma unroll 4
        for (int k = 0; k < 32; k++) {
            float4 w  = *(const float4*)&s_w[k][t4];
            float4 ua = *(const float4*)&s_u[k][n8];
            float4 ub = *(const float4*)&s_u[k][n8 + 4];
            float uu[8] = {ua.x, ua.y, ua.z, ua.w, ub.x, ub.y, ub.z, ub.w};
#pragma unroll
            for (int n = 0; n < 8; n++) {
                acc[n][0] += uu[n] * w.x;
                acc[n][1] += uu[n] * w.y;
                acc[n][2] += uu[n] * w.z;
                acc[n][3] += uu[n] * w.w;
            }
        }
        __syncthreads();
    }
    float4 bb = *(const float4*)&b1[t4];
#pragma unroll
    for (int n = 0; n < 8; n++) {
        int gn = node0 + n8 + n;
        if (gn < N_NODES) {
            float4 o;
            o.x = fmaxf(acc[n][0] + bb.x, 0.f);
            o.y = fmaxf(acc[n][1] + bb.y, 0.f);
            o.z = fmaxf(acc[n][2] + bb.z, 0.f);
            o.w = fmaxf(acc[n][3] + bb.w, 0.f);
            *(float4*)&g_h[gn * HID + t4] = o;
        }
    }
}

// ---------------- layer2 GEMM: out = agg2*inv @ W2l^T + h @ W2r^T + b2
// tile: 256 nodes x 32 outs, 256 threads, each thread 8 nodes x 4 outs, K chunked by 32.
__global__ void gemm2_kernel(const float* __restrict__ W2l,
                             const float* __restrict__ W2r,
                             const float* __restrict__ b2,
                             float* __restrict__ out) {
    __shared__ float s_u[32][264];   // [k][node]
    __shared__ float s_w[32][36];    // [k][t]
    int tid = threadIdx.x;
    int node0 = blockIdx.x * 256;
    int t4 = (tid & 7) * 4;
    int n8 = (tid >> 3) * 8;
    float acc[8][4];
#pragma unroll
    for (int n = 0; n < 8; n++)
#pragma unroll
        for (int j = 0; j < 4; j++) acc[n][j] = 0.f;

    for (int c = 0; c < 8; c++) {    // c<4: agg2*inv with W2l ; c>=4: h with W2r
        int koff = (c & 3) * 32;
        for (int idx = tid; idx < 256 * 32; idx += 256) {
            int n = idx >> 5, kk = idx & 31;
            int gn = node0 + n;
            float v = 0.f;
            if (gn < N_NODES)
                v = (c < 4) ? g_agg2[gn * HID + koff + kk] * g_inv[gn]
                            : g_h[gn * HID + koff + kk];
            s_u[kk][n] = v;
        }
        for (int idx = tid; idx < 32 * 32; idx += 256) {
            int t = idx >> 5, kk = idx & 31;
            s_w[kk][t] = (c < 4) ? W2l[t * HID + koff + kk]
                                 : W2r[t * HID + koff + kk];
        }
        __syncthreads();
#pragma unroll 4
        for (int k = 0; k < 32; k++) {
            float4 w  = *(const float4*)&s_w[k][t4];
            float4 ua = *(const float4*)&s_u[k][n8];
            float4 ub = *(const float4*)&s_u[k][n8 + 4];
            float uu[8] = {ua.x, ua.y, ua.z, ua.w, ub.x, ub.y, ub.z, ub.w};
#pragma unroll
            for (int n = 0; n < 8; n++) {
                acc[n][0] += uu[n] * w.x;
                acc[n][1] += uu[n] * w.y;
                acc[n][2] += uu[n] * w.z;
                acc[n][3] += uu[n] * w.w;
            }
        }
        __syncthreads();
    }
    float4 bb = *(const float4*)&b2[t4];
#pragma unroll
    for (int n = 0; n < 8; n++) {
        int gn = node0 + n8 + n;
        if (gn < N_NODES) {
            float4 o;
            o.x = acc[n][0] + bb.x;
            o.y = acc[n][1] + bb.y;
            o.z = acc[n][2] + bb.z;
            o.w = acc[n][3] + bb.w;
            *(float4*)&out[gn * OUT_CH + t4] = o;
        }
    }
}

// ---------------- launch ---------------------------------------------------
extern "C" void kernel_launch(void* const* d_in, const int* in_sizes, int n_in,
                              void* d_out, int out_size) {
    const float* x   = (const float*)d_in[0];
    const void*  ei  = d_in[1];
    const float* W1l = (const float*)d_in[2];
    const float* W1r = (const float*)d_in[3];
    const float* b1  = (const float*)d_in[4];
    const float* W2l = (const float*)d_in[5];
    const float* W2r = (const float*)d_in[6];
    const float* b2  = (const float*)d_in[7];
    float* out = (float*)d_out;

    const int TB = 256;
    int nb_nodes = (N_NODES + TB - 1) / TB;      // 391
    int nb_edges = (N_EDGES + TB - 1) / TB;      // 6250

    detect_kernel<<<1, 128>>>((const unsigned int*)ei);
    zero_cnt_kernel<<<nb_nodes, TB>>>();
    hist_kernel<<<nb_edges, TB>>>(ei);
    scan_kernel<<<1, 1024>>>();
    cursor_inv_kernel<<<nb_nodes, TB>>>();
    scatter_kernel<<<nb_edges, TB>>>(ei);

    agg1_kernel<<<(N_NODES + 7) / 8, TB>>>(x);                 // 12500 blocks
    gemm1_kernel<<<(N_NODES + 63) / 64, TB>>>(x, W1l, W1r, b1);// 1563 blocks
    agg2_kernel<<<(N_NODES + 7) / 8, TB>>>();                  // 12500 blocks
    gemm2_kernel<<<(N_NODES + 255) / 256, TB>>>(W2l, W2r, b2, out); // 391 blocks
}

// round 4
// speedup vs baseline: 1.4783x; 1.4783x over previous
#include <cuda_runtime.h>

#define N_NODES 100000
#define N_EDGES 1600000
#define IN_CH   32
#define HID     128
#define OUT_CH  32
#define SCAN_B  1024
#define N_SBLK  ((N_NODES + SCAN_B - 1) / SCAN_B)   // 98

// ---------------- scratch (device globals; no allocation allowed) ----------
__device__ __align__(16) int   g_cnt[N_NODES];
__device__ __align__(16) int   g_offp[N_NODES];         // per-block exclusive partials
__device__ __align__(16) int   g_off[N_NODES + 1];
__device__ __align__(16) int   g_bsum[N_SBLK];
__device__ __align__(16) int   g_boff[N_SBLK];
__device__ __align__(16) int   g_cur[N_NODES];
__device__ __align__(16) int   g_col[N_EDGES];          // src per dst-sorted edge
__device__ __align__(16) float g_inv[N_NODES];          // 1/max(deg,1)
__device__ __align__(16) float g_agg1[N_NODES * IN_CH]; // unscaled neighbor sum, layer1
__device__ __align__(16) float g_h[N_NODES * HID];      // relu(layer1)
__device__ __align__(16) float g_agg2[N_NODES * HID];   // unscaled neighbor sum, layer2
__device__ int g_is64;                                   // edge_index dtype flag

// ---------------- dtype detection: int64 vs int32 edge_index ---------------
__global__ void detect_kernel(const unsigned int* ei32) {
    __shared__ int flag;
    if (threadIdx.x == 0) flag = 0;
    __syncthreads();
    if (ei32[2 * threadIdx.x + 1] != 0u) flag = 1;
    __syncthreads();
    if (threadIdx.x == 0) g_is64 = flag ? 0 : 1;
}

__device__ __forceinline__ int load_idx(const void* ei, long long pos, int is64) {
    if (is64) return (int)((const long long*)ei)[pos];
    return ((const int*)ei)[pos];
}

// ---------------- CSR build ------------------------------------------------
__global__ void zero_cnt_kernel() {
    int i = blockIdx.x * blockDim.x + threadIdx.x;
    if (i < N_NODES) g_cnt[i] = 0;
}

__global__ void hist_kernel(const void* ei) {
    int e = blockIdx.x * blockDim.x + threadIdx.x;
    if (e >= N_EDGES) return;
    int is64 = g_is64;
    int d = load_idx(ei, (long long)N_EDGES + e, is64);
    atomicAdd(&g_cnt[d], 1);
}

// Phase 1: per-block scan (warp shuffle + cross-warp) -> partials + block sums
__global__ void scan_partial_kernel() {
    __shared__ int wsum[32];
    int tid = threadIdx.x;
    int lane = tid & 31, warp = tid >> 5;
    int i = blockIdx.x * SCAN_B + tid;
    int v = (i < N_NODES) ? g_cnt[i] : 0;
    int incl = v;
#pragma unroll
    for (int o = 1; o < 32; o <<= 1) {
        int t = __shfl_up_sync(0xffffffffu, incl, o);
        if (lane >= o) incl += t;
    }
    if (lane == 31) wsum[warp] = incl;
    __syncthreads();
    if (warp == 0) {
        int w = wsum[lane];
        int wincl = w;
#pragma unroll
        for (int o = 1; o < 32; o <<= 1) {
            int t = __shfl_up_sync(0xffffffffu, wincl, o);
            if (lane >= o) wincl += t;
        }
        wsum[lane] = wincl - w;   // exclusive warp offsets
        if (lane == 31) g_bsum[blockIdx.x] = wincl;
    }
    __syncthreads();
    if (i < N_NODES) g_offp[i] = incl - v + wsum[warp];
}

// Phase 2: scan the 98 block sums (tiny, single block)
__global__ void scan_bsum_kernel() {
    __shared__ int s[N_SBLK];
    int tid = threadIdx.x;
    if (tid < N_SBLK) s[tid] = g_bsum[tid];
    __syncthreads();
    if (tid == 0) {
        int run = 0;
        for (int b = 0; b < N_SBLK; b++) { int t = s[b]; s[b] = run; run += t; }
        g_off[N_NODES] = run;
    }
    __syncthreads();
    if (tid < N_SBLK) g_boff[tid] = s[tid];
}

// Phase 3 (fused): final offsets + cursors + inverse degree
__global__ void cursor_inv_kernel() {
    int i = blockIdx.x * blockDim.x + threadIdx.x;
    if (i < N_NODES) {
        int off = g_offp[i] + g_boff[i >> 10];
        g_off[i] = off;
        g_cur[i] = off;
        int d = g_cnt[i];
        g_inv[i] = 1.0f / (float)(d > 1 ? d : 1);
    }
}

__global__ void scatter_kernel(const void* ei) {
    int e = blockIdx.x * blockDim.x + threadIdx.x;
    if (e >= N_EDGES) return;
    int is64 = g_is64;
    int s = load_idx(ei, e, is64);
    int d = load_idx(ei, (long long)N_EDGES + e, is64);
    int p = atomicAdd(&g_cur[d], 1);
    g_col[p] = s;
}

// ---------------- aggregation (warp per dst node, gather, no float atomics)
__global__ void agg1_kernel(const float* __restrict__ x) {
    int node = blockIdx.x * 8 + (threadIdx.x >> 5);
    if (node >= N_NODES) return;
    int lane = threadIdx.x & 31;
    int b = g_off[node], e = g_off[node + 1];
    float acc = 0.f;
    for (int i = b; i < e; i++) {
        int s = g_col[i];                       // uniform across warp -> 1 request
        acc += x[s * IN_CH + lane];             // 128B coalesced row
    }
    g_agg1[node * IN_CH + lane] = acc;
}

__global__ void agg2_kernel() {
    int node = blockIdx.x * 8 + (threadIdx.x >> 5);
    if (node >= N_NODES) return;
    int lane = threadIdx.x & 31;
    int b = g_off[node], e = g_off[node + 1];
    const float4* h4 = (const float4*)g_h;
    float4 acc = make_float4(0.f, 0.f, 0.f, 0.f);
    for (int i = b; i < e; i++) {
        int s = g_col[i];
        float4 v = h4[s * 32 + lane];           // 512B coalesced row
        acc.x += v.x; acc.y += v.y; acc.z += v.z; acc.w += v.w;
    }
    ((float4*)g_agg2)[node * 32 + lane] = acc;
}

// ---------------- layer1 GEMM: h = relu(agg1*inv @ W1l^T + x @ W1r^T + b1)
__global__ void gemm1_kernel(const float* __restrict__ x,
                             const float* __restrict__ W1l,
                             const float* __restrict__ W1r,
                             const float* __restrict__ b1) {
    __shared__ float s_u[32][68];
    __shared__ float s_w[32][132];
    int tid = threadIdx.x;
    int node0 = blockIdx.x * 64;
    int t4 = (tid & 31) * 4;
    int n8 = (tid >> 5) * 8;
    float acc[8][4];
#pragma unroll
    for (int n = 0; n < 8; n++)
#pragma unroll
        for (int j = 0; j < 4; j++) acc[n][j] = 0.f;

    for (int c = 0; c < 2; c++) {
        for (int idx = tid; idx < 64 * 32; idx += 256) {
            int n = idx >> 5, kk = idx & 31;
            int gn = node0 + n;
            float v = 0.f;
            if (gn < N_NODES)
                v = c ? x[gn * 32 + kk] : g_agg1[gn * 32 + kk] * g_inv[gn];
            s_u[kk][n] = v;
        }
        for (int idx = tid; idx < 128 * 32; idx += 256) {
            int t = idx >> 5, kk = idx & 31;
            s_w[kk][t] = c ? W1r[t * 32 + kk] : W1l[t * 32 + kk];
        }
        __syncthreads();
#pragma unroll 4
        for (int k = 0; k < 32; k++) {
            float4 w  = *(const float4*)&s_w[k][t4];
            float4 ua = *(const float4*)&s_u[k][n8];
            float4 ub = *(const float4*)&s_u[k][n8 + 4];
            float uu[8] = {ua.x, ua.y, ua.z, ua.w, ub.x, ub.y, ub.z, ub.w};
#pragma unroll
            for (int n = 0; n < 8; n++) {
                acc[n][0] += uu[n] * w.x;
                acc[n][1] += uu[n] * w.y;
                acc[n][2] += uu[n] * w.z;
                acc[n][3] += uu[n] * w.w;
            }
        }
        __syncthreads();
    }
    float4 bb = *(const float4*)&b1[t4];
#pragma unroll
    for (int n = 0; n < 8; n++) {
        int gn = node0 + n8 + n;
        if (gn < N_NODES) {
            float4 o;
            o.x = fmaxf(acc[n][0] + bb.x, 0.f);
            o.y = fmaxf(acc[n][1] + bb.y, 0.f);
            o.z = fmaxf(acc[n][2] + bb.z, 0.f);
            o.w = fmaxf(acc[n][3] + bb.w, 0.f);
            *(float4*)&g_h[gn * HID + t4] = o;
        }
    }
}

// ---------------- layer2 GEMM: out = agg2*inv @ W2l^T + h @ W2r^T + b2
__global__ void gemm2_kernel(const float* __restrict__ W2l,
                             const float* __restrict__ W2r,
                             const float* __restrict__ b2,
                             float* __restrict__ out) {
    __shared__ float s_u[32][264];
    __shared__ float s_w[32][36];
    int tid = threadIdx.x;
    int node0 = blockIdx.x * 256;
    int t4 = (tid & 7) * 4;
    int n8 = (tid >> 3) * 8;
    float acc[8][4];
#pragma unroll
    for (int n = 0; n < 8; n++)
#pragma unroll
        for (int j = 0; j < 4; j++) acc[n][j] = 0.f;

    for (int c = 0; c < 8; c++) {
        int koff = (c & 3) * 32;
        for (int idx = tid; idx < 256 * 32; idx += 256) {
            int n = idx >> 5, kk = idx & 31;
            int gn = node0 + n;
            float v = 0.f;
            if (gn < N_NODES)
                v = (c < 4) ? g_agg2[gn * HID + koff + kk] * g_inv[gn]
                            : g_h[gn * HID + koff + kk];
            s_u[kk][n] = v;
        }
        for (int idx = tid; idx < 32 * 32; idx += 256) {
            int t = idx >> 5, kk = idx & 31;
            s_w[kk][t] = (c < 4) ? W2l[t * HID + koff + kk]
                                 : W2r[t * HID + koff + kk];
        }
        __syncthreads();
#pragma unroll 4
        for (int k = 0; k < 32; k++) {
            float4 w  = *(const float4*)&s_w[k][t4];
            float4 ua = *(const float4*)&s_u[k][n8];
            float4 ub = *(const float4*)&s_u[k][n8 + 4];
            float uu[8] = {ua.x, ua.y, ua.z, ua.w, ub.x, ub.y, ub.z, ub.w};
#pragma unroll
            for (int n = 0; n < 8; n++) {
                acc[n][0] += uu[n] * w.x;
                acc[n][1] += uu[n] * w.y;
                acc[n][2] += uu[n] * w.z;
                acc[n][3] += uu[n] * w.w;
            }
        }
        __syncthreads();
    }
    float4 bb = *(const float4*)&b2[t4];
#pragma unroll
    for (int n = 0; n < 8; n++) {
        int gn = node0 + n8 + n;
        if (gn < N_NODES) {
            float4 o;
            o.x = acc[n][0] + bb.x;
            o.y = acc[n][1] + bb.y;
            o.z = acc[n][2] + bb.z;
            o.w = acc[n][3] + bb.w;
            *(float4*)&out[gn * OUT_CH + t4] = o;
        }
    }
}

// ---------------- launch ---------------------------------------------------
extern "C" void kernel_launch(void* const* d_in, const int* in_sizes, int n_in,
                              void* d_out, int out_size) {
    const float* x   = (const float*)d_in[0];
    const void*  ei  = d_in[1];
    const float* W1l = (const float*)d_in[2];
    const float* W1r = (const float*)d_in[3];
    const float* b1  = (const float*)d_in[4];
    const float* W2l = (const float*)d_in[5];
    const float* W2r = (const float*)d_in[6];
    const float* b2  = (const float*)d_in[7];
    float* out = (float*)d_out;

    const int TB = 256;
    int nb_nodes = (N_NODES + TB - 1) / TB;      // 391
    int nb_edges = (N_EDGES + TB - 1) / TB;      // 6250

    detect_kernel<<<1, 128>>>((const unsigned int*)ei);
    zero_cnt_kernel<<<nb_nodes, TB>>>();
    hist_kernel<<<nb_edges, TB>>>(ei);
    scan_partial_kernel<<<N_SBLK, SCAN_B>>>();
    scan_bsum_kernel<<<1, 128>>>();
    cursor_inv_kernel<<<nb_nodes, TB>>>();
    scatter_kernel<<<nb_edges, TB>>>(ei);

    agg1_kernel<<<(N_NODES + 7) / 8, TB>>>(x);
    gemm1_kernel<<<(N_NODES + 63) / 64, TB>>>(x, W1l, W1r, b1);
    agg2_kernel<<<(N_NODES + 7) / 8, TB>>>();
    gemm2_kernel<<<(N_NODES + 255) / 256, TB>>>(W2l, W2r, b2, out);
}

// round 6
// speedup vs baseline: 1.6639x; 1.1255x over previous
#include <cuda_runtime.h>
#include <cuda_fp16.h>

#define N_NODES 100000
#define N_EDGES 1600000
#define IN_CH   32
#define HID     128
#define OUT_CH  32
#define SCAN_B  1024
#define N_SBLK  ((N_NODES + SCAN_B - 1) / SCAN_B)   // 98

// ---------------- scratch (device globals; no allocation allowed) ----------
__device__ __align__(16) int    g_cnt[N_NODES];
__device__ __align__(16) int    g_offp[N_NODES];
__device__ __align__(16) int    g_off[N_NODES + 1];
__device__ __align__(16) int    g_bsum[N_SBLK];
__device__ __align__(16) int    g_boff[N_SBLK];
__device__ __align__(16) int    g_cur[N_NODES];
__device__ __align__(16) int    g_col[N_EDGES];           // src per dst-sorted edge
__device__ __align__(16) float  g_inv[N_NODES];           // 1/max(deg,1)
__device__ __align__(16) __half2 g_xh2[N_NODES * 16];     // x in fp16 (gather copy)
__device__ __align__(16) float  g_agg1[N_NODES * IN_CH];  // fp32 neighbor sum, layer1
__device__ __align__(16) __half g_hf[N_NODES * HID];      // relu(layer1) in fp16
__device__ __align__(16) float  g_agg2[N_NODES * HID];    // fp32 neighbor sum, layer2
__device__ int g_is64;

// ---------------- dtype detection: int64 vs int32 edge_index ---------------
__global__ void detect_kernel(const unsigned int* ei32) {
    __shared__ int flag;
    if (threadIdx.x == 0) flag = 0;
    __syncthreads();
    if (ei32[2 * threadIdx.x + 1] != 0u) flag = 1;
    __syncthreads();
    if (threadIdx.x == 0) g_is64 = flag ? 0 : 1;
}

__device__ __forceinline__ int load_idx(const void* ei, long long pos, int is64) {
    if (is64) return (int)((const long long*)ei)[pos];
    return ((const int*)ei)[pos];
}

// ---------------- x -> fp16 copy (for gather path only) --------------------
__global__ void xhalf_kernel(const float* __restrict__ x) {
    int i = blockIdx.x * blockDim.x + threadIdx.x;   // over N_NODES*16 half2
    if (i < N_NODES * 16) {
        float2 v = ((const float2*)x)[i];
        g_xh2[i] = __floats2half2_rn(v.x, v.y);
    }
}

// ---------------- CSR build ------------------------------------------------
__global__ void zero_cnt_kernel() {
    int i = blockIdx.x * blockDim.x + threadIdx.x;
    if (i < N_NODES) g_cnt[i] = 0;
}

__global__ void hist_kernel(const void* ei) {
    int e = blockIdx.x * blockDim.x + threadIdx.x;
    if (e >= N_EDGES) return;
    int is64 = g_is64;
    int d = load_idx(ei, (long long)N_EDGES + e, is64);
    atomicAdd(&g_cnt[d], 1);
}

__global__ void scan_partial_kernel() {
    __shared__ int wsum[32];
    int tid = threadIdx.x;
    int lane = tid & 31, warp = tid >> 5;
    int i = blockIdx.x * SCAN_B + tid;
    int v = (i < N_NODES) ? g_cnt[i] : 0;
    int incl = v;
#pragma unroll
    for (int o = 1; o < 32; o <<= 1) {
        int t = __shfl_up_sync(0xffffffffu, incl, o);
        if (lane >= o) incl += t;
    }
    if (lane == 31) wsum[warp] = incl;
    __syncthreads();
    if (warp == 0) {
        int w = wsum[lane];
        int wincl = w;
#pragma unroll
        for (int o = 1; o < 32; o <<= 1) {
            int t = __shfl_up_sync(0xffffffffu, wincl, o);
            if (lane >= o) wincl += t;
        }
        wsum[lane] = wincl - w;
        if (lane == 31) g_bsum[blockIdx.x] = wincl;
    }
    __syncthreads();
    if (i < N_NODES) g_offp[i] = incl - v + wsum[warp];
}

__global__ void scan_bsum_kernel() {
    __shared__ int s[N_SBLK];
    int tid = threadIdx.x;
    if (tid < N_SBLK) s[tid] = g_bsum[tid];
    __syncthreads();
    if (tid == 0) {
        int run = 0;
        for (int b = 0; b < N_SBLK; b++) { int t = s[b]; s[b] = run; run += t; }
        g_off[N_NODES] = run;
    }
    __syncthreads();
    if (tid < N_SBLK) g_boff[tid] = s[tid];
}

__global__ void cursor_inv_kernel() {
    int i = blockIdx.x * blockDim.x + threadIdx.x;
    if (i < N_NODES) {
        int off = g_offp[i] + g_boff[i >> 10];
        g_off[i] = off;
        g_cur[i] = off;
        int d = g_cnt[i];
        g_inv[i] = 1.0f / (float)(d > 1 ? d : 1);
    }
}

__global__ void scatter_kernel(const void* ei) {
    int e = blockIdx.x * blockDim.x + threadIdx.x;
    if (e >= N_EDGES) return;
    int is64 = g_is64;
    int s = load_idx(ei, e, is64);
    int d = load_idx(ei, (long long)N_EDGES + e, is64);
    int p = atomicAdd(&g_cur[d], 1);
    g_col[p] = s;
}

// ---------------- aggregation 1: warp per node, 2 edges per iteration ------
// half-warp h (lane>>4) owns edge b+2i+h; lane&15 owns channel pair 2*(lane&15).
__global__ void agg1_kernel() {
    int node = blockIdx.x * 8 + (threadIdx.x >> 5);
    if (node >= N_NODES) return;
    int lane = threadIdx.x & 31;
    int half = lane >> 4;
    int ch2  = lane & 15;
    int b = g_off[node], e = g_off[node + 1];
    float2 acc = make_float2(0.f, 0.f);
    for (int i = b + half; i < e; i += 2) {
        int s = g_col[i];
        __half2 v = g_xh2[s * 16 + ch2];        // 64B per row, 2 rows per warp-iter
        float2 f = __half22float2(v);
        acc.x += f.x; acc.y += f.y;
    }
    acc.x += __shfl_xor_sync(0xffffffffu, acc.x, 16);
    acc.y += __shfl_xor_sync(0xffffffffu, acc.y, 16);
    if (half == 0)
        ((float2*)g_agg1)[node * 16 + ch2] = acc;
}

// ---------------- aggregation 2: warp per node, fp16 rows, LDG.64 ----------
__global__ void agg2_kernel() {
    int node = blockIdx.x * 8 + (threadIdx.x >> 5);
    if (node >= N_NODES) return;
    int lane = threadIdx.x & 31;
    int b = g_off[node], e = g_off[node + 1];
    const float2* h8 = (const float2*)g_hf;     // 8B = 4 half channels
    float4 acc = make_float4(0.f, 0.f, 0.f, 0.f);
    for (int i = b; i < e; i++) {
        int s = g_col[i];
        float2 raw = h8[s * 32 + lane];          // 256B coalesced row
        __half2 lo = *(__half2*)&raw.x;
        __half2 hi = *(__half2*)&raw.y;
        float2 fl = __half22float2(lo);
        float2 fh = __half22float2(hi);
        acc.x += fl.x; acc.y += fl.y; acc.z += fh.x; acc.w += fh.y;
    }
    ((float4*)g_agg2)[node * 32 + lane] = acc;   // channels lane*4..lane*4+3
}

// ---------------- layer1 GEMM: h = relu(agg1*inv @ W1l^T + x @ W1r^T + b1)
__global__ void gemm1_kernel(const float* __restrict__ x,
                             const float* __restrict__ W1l,
                             const float* __restrict__ W1r,
                             const float* __restrict__ b1) {
    __shared__ float s_u[32][68];
    __shared__ float s_w[32][132];
    int tid = threadIdx.x;
    int node0 = blockIdx.x * 64;
    int t4 = (tid & 31) * 4;
    int n8 = (tid >> 5) * 8;
    float acc[8][4];
#pragma unroll
    for (int n = 0; n < 8; n++)
#pragma unroll
        for (int j = 0; j < 4; j++) acc[n][j] = 0.f;

    for (int c = 0; c < 2; c++) {
        for (int idx = tid; idx < 64 * 32; idx += 256) {
            int n = idx >> 5, kk = idx & 31;
            int gn = node0 + n;
            float v = 0.f;
            if (gn < N_NODES)
                v = c ? x[gn * 32 + kk] : g_agg1[gn * 32 + kk] * g_inv[gn];
            s_u[kk][n] = v;
        }
        for (int idx = tid; idx < 128 * 32; idx += 256) {
            int t = idx >> 5, kk = idx & 31;
            s_w[kk][t] = c ? W1r[t * 32 + kk] : W1l[t * 32 + kk];
        }
        __syncthreads();
#pragma unroll 4
        for (int k = 0; k < 32; k++) {
            float4 w  = *(const float4*)&s_w[k][t4];
            float4 ua = *(const float4*)&s_u[k][n8];
            float4 ub = *(const float4*)&s_u[k][n8 + 4];
            float uu[8] = {ua.x, ua.y, ua.z, ua.w, ub.x, ub.y, ub.z, ub.w};
#pragma unroll
            for (int n = 0; n < 8; n++) {
                acc[n][0] += uu[n] * w.x;
                acc[n][1] += uu[n] * w.y;
                acc[n][2] += uu[n] * w.z;
                acc[n][3] += uu[n] * w.w;
            }
        }
        __syncthreads();
    }
    float4 bb = *(const float4*)&b1[t4];
#pragma unroll
    for (int n = 0; n < 8; n++) {
        int gn = node0 + n8 + n;
        if (gn < N_NODES) {
            float ox = fmaxf(acc[n][0] + bb.x, 0.f);
            float oy = fmaxf(acc[n][1] + bb.y, 0.f);
            float oz = fmaxf(acc[n][2] + bb.z, 0.f);
            float ow = fmaxf(acc[n][3] + bb.w, 0.f);
            __half2 p0 = __floats2half2_rn(ox, oy);
            __half2 p1 = __floats2half2_rn(oz, ow);
            uint2 pk;
            pk.x = *(unsigned int*)&p0;
            pk.y = *(unsigned int*)&p1;
            ((uint2*)g_hf)[gn * 32 + (t4 >> 2)] = pk;   // 4 half channels, 8B store
        }
    }
}

// ---------------- layer2 GEMM: out = agg2*inv @ W2l^T + h @ W2r^T + b2
__global__ void gemm2_kernel(const float* __restrict__ W2l,
                             const float* __restrict__ W2r,
                             const float* __restrict__ b2,
                             float* __restrict__ out) {
    __shared__ float s_u[32][264];
    __shared__ float s_w[32][36];
    int tid = threadIdx.x;
    int node0 = blockIdx.x * 256;
    int t4 = (tid & 7) * 4;
    int n8 = (tid >> 3) * 8;
    float acc[8][4];
#pragma unroll
    for (int n = 0; n < 8; n++)
#pragma unroll
        for (int j = 0; j < 4; j++) acc[n][j] = 0.f;

    for (int c = 0; c < 8; c++) {
        int koff = (c & 3) * 32;
        for (int idx = tid; idx < 256 * 32; idx += 256) {
            int n = idx >> 5, kk = idx & 31;
            int gn = node0 + n;
            float v = 0.f;
            if (gn < N_NODES)
                v = (c < 4) ? g_agg2[gn * HID + koff + kk] * g_inv[gn]
                            : __half2float(g_hf[gn * HID + koff + kk]);
            s_u[kk][n] = v;
        }
        for (int idx = tid; idx < 32 * 32; idx += 256) {
            int t = idx >> 5, kk = idx & 31;
            s_w[kk][t] = (c < 4) ? W2l[t * HID + koff + kk]
                                 : W2r[t * HID + koff + kk];
        }
        __syncthreads();
#pragma unroll 4
        for (int k = 0; k < 32; k++) {
            float4 w  = *(const float4*)&s_w[k][t4];
            float4 ua = *(const float4*)&s_u[k][n8];
            float4 ub = *(const float4*)&s_u[k][n8 + 4];
            float uu[8] = {ua.x, ua.y, ua.z, ua.w, ub.x, ub.y, ub.z, ub.w};
#pragma unroll
            for (int n = 0; n < 8; n++) {
                acc[n][0] += uu[n] * w.x;
                acc[n][1] += uu[n] * w.y;
                acc[n][2] += uu[n] * w.z;
                acc[n][3] += uu[n] * w.w;
            }
        }
        __syncthreads();
    }
    float4 bb = *(const float4*)&b2[t4];
#pragma unroll
    for (int n = 0; n < 8; n++) {
        int gn = node0 + n8 + n;
        if (gn < N_NODES) {
            float4 o;
            o.x = acc[n][0] + bb.x;
            o.y = acc[n][1] + bb.y;
            o.z = acc[n][2] + bb.z;
            o.w = acc[n][3] + bb.w;
            *(float4*)&out[gn * OUT_CH + t4] = o;
        }
    }
}

// ---------------- launch ---------------------------------------------------
extern "C" void kernel_launch(void* const* d_in, const int* in_sizes, int n_in,
                              void* d_out, int out_size) {
    const float* x   = (const float*)d_in[0];
    const void*  ei  = d_in[1];
    const float* W1l = (const float*)d_in[2];
    const float* W1r = (const float*)d_in[3];
    const float* b1  = (const float*)d_in[4];
    const float* W2l = (const float*)d_in[5];
    const float* W2r = (const float*)d_in[6];
    const float* b2  = (const float*)d_in[7];
    float* out = (float*)d_out;

    const int TB = 256;
    int nb_nodes = (N_NODES + TB - 1) / TB;      // 391
    int nb_edges = (N_EDGES + TB - 1) / TB;      // 6250

    detect_kernel<<<1, 128>>>((const unsigned int*)ei);
    zero_cnt_kernel<<<nb_nodes, TB>>>();
    xhalf_kernel<<<(N_NODES * 16 + TB - 1) / TB, TB>>>(x);
    hist_kernel<<<nb_edges, TB>>>(ei);
    scan_partial_kernel<<<N_SBLK, SCAN_B>>>();
    scan_bsum_kernel<<<1, 128>>>();
    cursor_inv_kernel<<<nb_nodes, TB>>>();
    scatter_kernel<<<nb_edges, TB>>>(ei);

    agg1_kernel<<<(N_NODES + 7) / 8, TB>>>();
    gemm1_kernel<<<(N_NODES + 63) / 64, TB>>>(x, W1l, W1r, b1);
    agg2_kernel<<<(N_NODES + 7) / 8, TB>>>();
    gemm2_kernel<<<(N_NODES + 255) / 256, TB>>>(W2l, W2r, b2, out);
}

// round 8
// speedup vs baseline: 2.1562x; 1.2959x over previous
#include <cuda_runtime.h>
#include <cuda_fp16.h>

#define N_NODES 100000
#define N_EDGES 1600000
#define IN_CH   32
#define HID     128
#define OUT_CH  32
#define SCAN_B  1024
#define N_SBLK  ((N_NODES + SCAN_B - 1) / SCAN_B)   // 98

// ---------------- scratch (device globals; no allocation allowed) ----------
__device__ __align__(16) int    g_cnt[N_NODES];
__device__ __align__(16) int    g_offp[N_NODES];
__device__ __align__(16) int    g_off[N_NODES + 1];
__device__ __align__(16) int    g_bsum[N_SBLK];
__device__ __align__(16) int    g_boff[N_SBLK];
__device__ __align__(16) int    g_cur[N_NODES];
__device__ __align__(16) int    g_col[N_EDGES];
__device__ __align__(16) float  g_inv[N_NODES];
__device__ __align__(16) __half2 g_xh2[N_NODES * 16];     // x in fp16
__device__ __align__(16) float  g_agg1[N_NODES * IN_CH];  // fp32 neighbor sum, L1
__device__ __align__(16) __half g_hf[N_NODES * HID];      // relu(L1) fp16
__device__ __align__(16) float  g_agg2[N_NODES * HID];    // fp32 neighbor sum, L2
__device__ __align__(16) __half g_w1h[128 * 64];          // [W1l | W1r] fp16, [out][k]
__device__ __align__(16) __half g_w2h[32 * 256];          // [W2l | W2r] fp16, [out][k]
__device__ int g_is64;

static __device__ __forceinline__ unsigned smem_u32(const void* p) {
    unsigned r;
    asm("{ .reg .u64 t; cvta.to.shared.u64 t, %1; cvt.u32.u64 %0, t; }"
        : "=r"(r) : "l"(p));
    return r;
}

#define LDMATRIX_X4(a0,a1,a2,a3,addr) \
    asm volatile("ldmatrix.sync.aligned.m8n8.x4.shared.b16 {%0,%1,%2,%3}, [%4];" \
        : "=r"(a0),"=r"(a1),"=r"(a2),"=r"(a3) : "r"(addr))
#define LDMATRIX_X2(b0,b1,addr) \
    asm volatile("ldmatrix.sync.aligned.m8n8.x2.shared.b16 {%0,%1}, [%2];" \
        : "=r"(b0),"=r"(b1) : "r"(addr))
#define MMA16816(d,a0,a1,a2,a3,b0,b1) \
    asm volatile("mma.sync.aligned.m16n8k16.row.col.f32.f16.f16.f32 " \
        "{%0,%1,%2,%3}, {%4,%5,%6,%7}, {%8,%9}, {%0,%1,%2,%3};" \
        : "+f"(d[0]),"+f"(d[1]),"+f"(d[2]),"+f"(d[3]) \
        : "r"(a0),"r"(a1),"r"(a2),"r"(a3),"r"(b0),"r"(b1))

// ---------------- dtype detection ------------------------------------------
__global__ void detect_kernel(const unsigned int* ei32) {
    __shared__ int flag;
    if (threadIdx.x == 0) flag = 0;
    __syncthreads();
    if (ei32[2 * threadIdx.x + 1] != 0u) flag = 1;
    __syncthreads();
    if (threadIdx.x == 0) g_is64 = flag ? 0 : 1;
}

__device__ __forceinline__ int load_idx(const void* ei, long long pos, int is64) {
    if (is64) return (int)((const long long*)ei)[pos];
    return ((const int*)ei)[pos];
}

// ---------------- one-time fp16 conversions --------------------------------
__global__ void xhalf_kernel(const float* __restrict__ x) {
    int i = blockIdx.x * blockDim.x + threadIdx.x;
    if (i < N_NODES * 16) {
        float2 v = ((const float2*)x)[i];
        g_xh2[i] = __floats2half2_rn(v.x, v.y);
    }
}

__global__ void wconv1_kernel(const float* __restrict__ W1l,
                              const float* __restrict__ W1r) {
    int i = blockIdx.x * blockDim.x + threadIdx.x;   // 128*64
    if (i < 128 * 64) {
        int row = i >> 6, k = i & 63;
        float v = (k < 32) ? W1l[row * 32 + k] : W1r[row * 32 + (k - 32)];
        g_w1h[i] = __float2half_rn(v);
    }
}

__global__ void wconv2_kernel(const float* __restrict__ W2l,
                              const float* __restrict__ W2r) {
    int i = blockIdx.x * blockDim.x + threadIdx.x;   // 32*256
    if (i < 32 * 256) {
        int row = i >> 8, k = i & 255;
        float v = (k < 128) ? W2l[row * 128 + k] : W2r[row * 128 + (k - 128)];
        g_w2h[i] = __float2half_rn(v);
    }
}

// ---------------- CSR build ------------------------------------------------
__global__ void zero_cnt_kernel() {
    int i = blockIdx.x * blockDim.x + threadIdx.x;
    if (i < N_NODES) g_cnt[i] = 0;
}

__global__ void hist_kernel(const void* ei) {
    int e = blockIdx.x * blockDim.x + threadIdx.x;
    if (e >= N_EDGES) return;
    int is64 = g_is64;
    int d = load_idx(ei, (long long)N_EDGES + e, is64);
    atomicAdd(&g_cnt[d], 1);
}

__global__ void scan_partial_kernel() {
    __shared__ int wsum[32];
    int tid = threadIdx.x;
    int lane = tid & 31, warp = tid >> 5;
    int i = blockIdx.x * SCAN_B + tid;
    int v = (i < N_NODES) ? g_cnt[i] : 0;
    int incl = v;
#pragma unroll
    for (int o = 1; o < 32; o <<= 1) {
        int t = __shfl_up_sync(0xffffffffu, incl, o);
        if (lane >= o) incl += t;
    }
    if (lane == 31) wsum[warp] = incl;
    __syncthreads();
    if (warp == 0) {
        int w = wsum[lane];
        int wincl = w;
#pragma unroll
        for (int o = 1; o < 32; o <<= 1) {
            int t = __shfl_up_sync(0xffffffffu, wincl, o);
            if (lane >= o) wincl += t;
        }
        wsum[lane] = wincl - w;
        if (lane == 31) g_bsum[blockIdx.x] = wincl;
    }
    __syncthreads();
    if (i < N_NODES) g_offp[i] = incl - v + wsum[warp];
}

__global__ void scan_bsum_kernel() {
    __shared__ int s[N_SBLK];
    int tid = threadIdx.x;
    if (tid < N_SBLK) s[tid] = g_bsum[tid];
    __syncthreads();
    if (tid == 0) {
        int run = 0;
        for (int b = 0; b < N_SBLK; b++) { int t = s[b]; s[b] = run; run += t; }
        g_off[N_NODES] = run;
    }
    __syncthreads();
    if (tid < N_SBLK) g_boff[tid] = s[tid];
}

__global__ void cursor_inv_kernel() {
    int i = blockIdx.x * blockDim.x + threadIdx.x;
    if (i < N_NODES) {
        int off = g_offp[i] + g_boff[i >> 10];
        g_off[i] = off;
        g_cur[i] = off;
        int d = g_cnt[i];
        g_inv[i] = 1.0f / (float)(d > 1 ? d : 1);
    }
}

__global__ void scatter_kernel(const void* ei) {
    int e = blockIdx.x * blockDim.x + threadIdx.x;
    if (e >= N_EDGES) return;
    int is64 = g_is64;
    int s = load_idx(ei, e, is64);
    int d = load_idx(ei, (long long)N_EDGES + e, is64);
    int p = atomicAdd(&g_cur[d], 1);
    g_col[p] = s;
}

// ---------------- aggregation 1: warp/node, 2 edges per iteration ----------
__global__ void agg1_kernel() {
    int node = blockIdx.x * 8 + (threadIdx.x >> 5);
    if (node >= N_NODES) return;
    int lane = threadIdx.x & 31;
    int half = lane >> 4;
    int ch2  = lane & 15;
    int b = g_off[node], e = g_off[node + 1];
    float2 acc = make_float2(0.f, 0.f);
    for (int i = b + half; i < e; i += 2) {
        int s = g_col[i];
        __half2 v = g_xh2[s * 16 + ch2];
        float2 f = __half22float2(v);
        acc.x += f.x; acc.y += f.y;
    }
    acc.x += __shfl_xor_sync(0xffffffffu, acc.x, 16);
    acc.y += __shfl_xor_sync(0xffffffffu, acc.y, 16);
    if (half == 0)
        ((float2*)g_agg1)[node * 16 + ch2] = acc;
}

// ---------------- aggregation 2: warp/node, 2 edges/iter, uint4 loads ------
__global__ void agg2_kernel() {
    int node = blockIdx.x * 8 + (threadIdx.x >> 5);
    if (node >= N_NODES) return;
    int lane = threadIdx.x & 31;
    int half = lane >> 4;
    int l16  = lane & 15;
    int b = g_off[node], e = g_off[node + 1];
    const uint4* h16 = (const uint4*)g_hf;      // 16B = 8 half channels
    float acc[8];
#pragma unroll
    for (int j = 0; j < 8; j++) acc[j] = 0.f;
    for (int i = b + half; i < e; i += 2) {
        int s = g_col[i];
        uint4 raw = h16[s * 16 + l16];          // 256B row across 16 lanes
        __half2 p0 = *(__half2*)&raw.x;
        __half2 p1 = *(__half2*)&raw.y;
        __half2 p2 = *(__half2*)&raw.z;
        __half2 p3 = *(__half2*)&raw.w;
        float2 f0 = __half22float2(p0), f1 = __half22float2(p1);
        float2 f2 = __half22float2(p2), f3 = __half22float2(p3);
        acc[0] += f0.x; acc[1] += f0.y; acc[2] += f1.x; acc[3] += f1.y;
        acc[4] += f2.x; acc[5] += f2.y; acc[6] += f3.x; acc[7] += f3.y;
    }
#pragma unroll
    for (int j = 0; j < 8; j++)
        acc[j] += __shfl_xor_sync(0xffffffffu, acc[j], 16);
    if (half == 0) {
        float4 o0 = make_float4(acc[0], acc[1], acc[2], acc[3]);
        float4 o1 = make_float4(acc[4], acc[5], acc[6], acc[7]);
        *(float4*)&g_agg2[node * 128 + l16 * 8]     = o0;
        *(float4*)&g_agg2[node * 128 + l16 * 8 + 4] = o1;
    }
}

// ---------------- layer1 GEMM via tensor cores -----------------------------
// h = relu([agg1*inv | x] @ [W1l|W1r]^T + b1), tile 64 nodes x 128 outs, 4 warps.
__global__ void gemm1_mma(const float* __restrict__ b1) {
    __shared__ __half sA[64 * 72];     // [node][k0..63], stride 72
    __shared__ __half sB[128 * 72];    // [out][k0..63], stride 72
    int tid = threadIdx.x, lane = tid & 31, warp = tid >> 5;
    int node0 = blockIdx.x * 64;

    // weights: 128x64 halves = 1024 uint4
    for (int idx = tid; idx < 1024; idx += 128) {
        int row = idx >> 3, c8 = (idx & 7) * 8;
        *(uint4*)&sB[row * 72 + c8] = *(const uint4*)&g_w1h[row * 64 + c8];
    }
    // A k=0..31: agg1 * inv (fp32 -> fp16)
    for (int idx = tid; idx < 512; idx += 128) {
        int row = idx >> 3, s4 = (idx & 7) * 4;
        int gn = node0 + row;
        float4 v = make_float4(0.f, 0.f, 0.f, 0.f);
        float sc = 0.f;
        if (gn < N_NODES) { v = *(const float4*)&g_agg1[gn * 32 + s4]; sc = g_inv[gn]; }
        __half2 h0 = __floats2half2_rn(v.x * sc, v.y * sc);
        __half2 h1 = __floats2half2_rn(v.z * sc, v.w * sc);
        uint2 pk;
        pk.x = *(unsigned*)&h0; pk.y = *(unsigned*)&h1;
        *(uint2*)&sA[row * 72 + s4] = pk;
    }
    // A k=32..63: x fp16 copy
    for (int idx = tid; idx < 256; idx += 128) {
        int row = idx >> 2, q = idx & 3;
        int gn = node0 + row;
        uint4 v = make_uint4(0u, 0u, 0u, 0u);
        if (gn < N_NODES) v = ((const uint4*)g_xh2)[gn * 4 + q];
        *(uint4*)&sA[row * 72 + 32 + q * 8] = v;
    }
    __syncthreads();

    float d[16][4];
#pragma unroll
    for (int t = 0; t < 16; t++)
        d[t][0] = d[t][1] = d[t][2] = d[t][3] = 0.f;

    int ar = (lane & 7) + ((lane >> 3) & 1) * 8;
    int ac = (lane >> 4) * 8;
    int br = lane & 7;
    int bc = ((lane >> 3) & 1) * 8;

#pragma unroll
    for (int ks = 0; ks < 4; ks++) {
        int k0 = ks * 16;
        unsigned a0, a1, a2, a3;
        unsigned addrA = smem_u32(&sA[(warp * 16 + ar) * 72 + k0 + ac]);
        LDMATRIX_X4(a0, a1, a2, a3, addrA);
#pragma unroll
        for (int t = 0; t < 16; t++) {
            unsigned b0, b1;
            unsigned addrB = smem_u32(&sB[(t * 8 + br) * 72 + k0 + bc]);
            LDMATRIX_X2(b0, b1, addrB);
            MMA16816(d[t], a0, a1, a2, a3, b0, b1);
        }
    }

    int g = lane >> 2, tg = lane & 3;
    int nA = node0 + warp * 16 + g;
    int nB = nA + 8;
#pragma unroll
    for (int t = 0; t < 16; t++) {
        int col = t * 8 + tg * 2;
        float bx = b1[col], by = b1[col + 1];
        if (nA < N_NODES) {
            __half2 h = __floats2half2_rn(fmaxf(d[t][0] + bx, 0.f),
                                          fmaxf(d[t][1] + by, 0.f));
            *(__half2*)&g_hf[nA * 128 + col] = h;
        }
        if (nB < N_NODES) {
            __half2 h = __floats2half2_rn(fmaxf(d[t][2] + bx, 0.f),
                                          fmaxf(d[t][3] + by, 0.f));
            *(__half2*)&g_hf[nB * 128 + col] = h;
        }
    }
}

// ---------------- layer2 GEMM via tensor cores -----------------------------
// out = [agg2*inv | h] @ [W2l|W2r]^T + b2, tile 128 nodes x 32 outs, 4 warps.
__global__ void gemm2_mma(const float* __restrict__ b2, float* __restrict__ out) {
    __shared__ __half sA[128 * 72];    // [node][k-chunk 64], stride 72
    __shared__ __half sB[32 * 264];    // [out][k 0..255], stride 264
    int tid = threadIdx.x, lane = tid & 31, warp = tid >> 5;
    int node0 = blockIdx.x * 128;

    for (int idx = tid; idx < 1024; idx += 128) {
        int row = idx >> 5, s8 = (idx & 31) * 8;
        *(uint4*)&sB[row * 264 + s8] = *(const uint4*)&g_w2h[row * 256 + s8];
    }

    float d[8][4];
#pragma unroll
    for (int t = 0; t < 8; t++)
        d[t][0] = d[t][1] = d[t][2] = d[t][3] = 0.f;

    int ar = (lane & 7) + ((lane >> 3) & 1) * 8;
    int ac = (lane >> 4) * 8;
    int br = lane & 7;
    int bc = ((lane >> 3) & 1) * 8;

    for (int chunk = 0; chunk < 4; chunk++) {
        if (chunk) __syncthreads();    // protect sA reuse
        if (chunk < 2) {
            // agg2 * inv (fp32 -> fp16), k-global = chunk*64 + 0..63
            for (int idx = tid; idx < 2048; idx += 128) {
                int row = idx >> 4, s4 = (idx & 15) * 4;
                int gn = node0 + row;
                float4 v = make_float4(0.f, 0.f, 0.f, 0.f);
                float sc = 0.f;
                if (gn < N_NODES) {
                    v = *(const float4*)&g_agg2[gn * 128 + chunk * 64 + s4];
                    sc = g_inv[gn];
                }
                __half2 h0 = __floats2half2_rn(v.x * sc, v.y * sc);
                __half2 h1 = __floats2half2_rn(v.z * sc, v.w * sc);
                uint2 pk;
                pk.x = *(unsigned*)&h0; pk.y = *(unsigned*)&h1;
                *(uint2*)&sA[row * 72 + s4] = pk;
            }
        } else {
            // h fp16 copy, k-global = 128 + (chunk-2)*64 + 0..63
            for (int idx = tid; idx < 1024; idx += 128) {
                int row = idx >> 3, q = idx & 7;
                int gn = node0 + row;
                uint4 v = make_uint4(0u, 0u, 0u, 0u);
                if (gn < N_NODES)
                    v = ((const uint4*)g_hf)[gn * 16 + (chunk - 2) * 8 + q];
                *(uint4*)&sA[row * 72 + q * 8] = v;
            }
        }
        __syncthreads();

#pragma unroll
        for (int ks = 0; ks < 4; ks++) {
            int k0 = ks * 16;
            unsigned bf[4][2];
#pragma unroll
            for (int nt = 0; nt < 4; nt++) {
                unsigned addrB = smem_u32(&sB[(nt * 8 + br) * 264 + chunk * 64 + k0 + bc]);
                LDMATRIX_X2(bf[nt][0], bf[nt][1], addrB);
            }
#pragma unroll
            for (int mt = 0; mt < 2; mt++) {
                unsigned a0, a1, a2, a3;
                unsigned addrA = smem_u32(&sA[(warp * 32 + mt * 16 + ar) * 72 + k0 + ac]);
                LDMATRIX_X4(a0, a1, a2, a3, addrA);
#pragma unroll
                for (int nt = 0; nt < 4; nt++)
                    MMA16816(d[mt * 4 + nt], a0, a1, a2, a3, bf[nt][0], bf[nt][1]);
            }
        }
    }

    int g = lane >> 2, tg = lane & 3;
#pragma unroll
    for (int mt = 0; mt < 2; mt++) {
        int nA = node0 + warp * 32 + mt * 16 + g;
        int nB = nA + 8;
#pragma unroll
        for (int nt = 0; nt < 4; nt++) {
            int col = nt * 8 + tg * 2;
            float bx = b2[col], by = b2[col + 1];
            float* dd = d[mt * 4 + nt];
            if (nA < N_NODES) {
                float2 o = make_float2(dd[0] + bx, dd[1] + by);
                *(float2*)&out[nA * 32 + col] = o;
            }
            if (nB < N_NODES) {
                float2 o = make_float2(dd[2] + bx, dd[3] + by);
                *(float2*)&out[nB * 32 + col] = o;
            }
        }
    }
}

// ---------------- launch ---------------------------------------------------
extern "C" void kernel_launch(void* const* d_in, const int* in_sizes, int n_in,
                              void* d_out, int out_size) {
    const float* x   = (const float*)d_in[0];
    const void*  ei  = d_in[1];
    const float* W1l = (const float*)d_in[2];
    const float* W1r = (const float*)d_in[3];
    const float* b1  = (const float*)d_in[4];
    const float* W2l = (const float*)d_in[5];
    const float* W2r = (const float*)d_in[6];
    const float* b2  = (const float*)d_in[7];
    float* out = (float*)d_out;

    const int TB = 256;
    int nb_nodes = (N_NODES + TB - 1) / TB;
    int nb_edges = (N_EDGES + TB - 1) / TB;

    detect_kernel<<<1, 128>>>((const unsigned int*)ei);
    zero_cnt_kernel<<<nb_nodes, TB>>>();
    xhalf_kernel<<<(N_NODES * 16 + TB - 1) / TB, TB>>>(x);
    wconv1_kernel<<<(128 * 64 + TB - 1) / TB, TB>>>(W1l, W1r);
    wconv2_kernel<<<(32 * 256 + TB - 1) / TB, TB>>>(W2l, W2r);
    hist_kernel<<<nb_edges, TB>>>(ei);
    scan_partial_kernel<<<N_SBLK, SCAN_B>>>();
    scan_bsum_kernel<<<1, 128>>>();
    cursor_inv_kernel<<<nb_nodes, TB>>>();
    scatter_kernel<<<nb_edges, TB>>>(ei);

    agg1_kernel<<<(N_NODES + 7) / 8, TB>>>();
    gemm1_mma<<<(N_NODES + 63) / 64, 128>>>(b1);
    agg2_kernel<<<(N_NODES + 7) / 8, TB>>>();
    gemm2_mma<<<(N_NODES + 127) / 128, 128>>>(b2, out);
}

// round 9
// speedup vs baseline: 2.8054x; 1.3011x over previous
#include <cuda_runtime.h>
#include <cuda_fp16.h>

#define N_NODES 100000
#define N_EDGES 1600000
#define IN_CH   32
#define HID     128
#define OUT_CH  32
#define SCAN_B  1024
#define N_SBLK  ((N_NODES + SCAN_B - 1) / SCAN_B)   // 98

// prep_kernel block ranges
#define PB_XHALF 3125              // 3125*512 = 1.6M half2
#define PB_ZERO  (PB_XHALF + 391)
#define PB_W1    (PB_ZERO + 32)
#define PB_W2    (PB_W1 + 32)
#define PB_TOT   (PB_W2 + 1)       // +1 detect block

// ---------------- scratch (device globals; no allocation allowed) ----------
__device__ __align__(16) int    g_cnt[N_NODES];
__device__ __align__(16) int    g_offp[N_NODES];
__device__ __align__(16) int    g_off[N_NODES + 1];
__device__ __align__(16) int    g_bsum[N_SBLK];
__device__ __align__(16) int    g_boff[N_SBLK];
__device__ __align__(16) int    g_cur[N_NODES];
__device__ __align__(16) int    g_col[N_EDGES];
__device__ __align__(16) float  g_inv[N_NODES];
__device__ __align__(16) __half2 g_xh2[N_NODES * 16];     // x fp16, 64B rows
__device__ __align__(16) float  g_agg1[N_NODES * IN_CH];  // fp32 sum, L1
__device__ __align__(16) __half g_hf[N_NODES * HID];      // relu(L1) fp16
__device__ __align__(16) __half g_pf[N_NODES * OUT_CH];   // p = h @ W2l^T fp16
__device__ __align__(16) float  g_aggp[N_NODES * OUT_CH]; // mean_agg(p) fp32
__device__ __align__(16) __half g_w1h[128 * 64];          // [W1l | W1r] fp16
__device__ __align__(16) __half g_w2h[32 * 256];          // [W2l | W2r] fp16
__device__ int g_is64;

static __device__ __forceinline__ unsigned smem_u32(const void* p) {
    unsigned r;
    asm("{ .reg .u64 t; cvta.to.shared.u64 t, %1; cvt.u32.u64 %0, t; }"
        : "=r"(r) : "l"(p));
    return r;
}

#define LDMATRIX_X4(a0,a1,a2,a3,addr) \
    asm volatile("ldmatrix.sync.aligned.m8n8.x4.shared.b16 {%0,%1,%2,%3}, [%4];" \
        : "=r"(a0),"=r"(a1),"=r"(a2),"=r"(a3) : "r"(addr))
#define LDMATRIX_X2(b0,b1,addr) \
    asm volatile("ldmatrix.sync.aligned.m8n8.x2.shared.b16 {%0,%1}, [%2];" \
        : "=r"(b0),"=r"(b1) : "r"(addr))
#define MMA16816(d,a0,a1,a2,a3,b0,b1) \
    asm volatile("mma.sync.aligned.m16n8k16.row.col.f32.f16.f16.f32 " \
        "{%0,%1,%2,%3}, {%4,%5,%6,%7}, {%8,%9}, {%0,%1,%2,%3};" \
        : "+f"(d[0]),"+f"(d[1]),"+f"(d[2]),"+f"(d[3]) \
        : "r"(a0),"r"(a1),"r"(a2),"r"(a3),"r"(b0),"r"(b1))

// ---------------- prep: xhalf + zero_cnt + wconv1 + wconv2 + detect --------
__global__ void prep_kernel(const float* __restrict__ x,
                            const float* __restrict__ W1l,
                            const float* __restrict__ W1r,
                            const float* __restrict__ W2l,
                            const float* __restrict__ W2r,
                            const unsigned int* __restrict__ ei32) {
    int b = blockIdx.x, tid = threadIdx.x;
    if (b < PB_XHALF) {
        int i = b * 512 + tid;
        float2 v0 = ((const float2*)x)[i];
        g_xh2[i] = __floats2half2_rn(v0.x, v0.y);
        int i2 = i + 256;
        float2 v1 = ((const float2*)x)[i2];
        g_xh2[i2] = __floats2half2_rn(v1.x, v1.y);
    } else if (b < PB_ZERO) {
        int i = (b - PB_XHALF) * 256 + tid;
        if (i < N_NODES) g_cnt[i] = 0;
    } else if (b < PB_W1) {
        int i = (b - PB_ZERO) * 256 + tid;      // 8192 = 128*64
        int row = i >> 6, k = i & 63;
        float v = (k < 32) ? W1l[row * 32 + k] : W1r[row * 32 + (k - 32)];
        g_w1h[i] = __float2half_rn(v);
    } else if (b < PB_W2) {
        int i = (b - PB_W1) * 256 + tid;        // 8192 = 32*256
        int row = i >> 8, k = i & 255;
        float v = (k < 128) ? W2l[row * 128 + k] : W2r[row * 128 + (k - 128)];
        g_w2h[i] = __float2half_rn(v);
    } else {
        __shared__ int flag;
        if (tid == 0) flag = 0;
        __syncthreads();
        if (tid < 128 && ei32[2 * tid + 1] != 0u) flag = 1;
        __syncthreads();
        if (tid == 0) g_is64 = flag ? 0 : 1;
    }
}

// ---------------- CSR build (2 edges per thread) ---------------------------
__global__ void hist_kernel(const void* ei) {
    int e2 = blockIdx.x * blockDim.x + threadIdx.x;
    if (e2 >= N_EDGES / 2) return;
    if (g_is64) {
        longlong2 d = ((const longlong2*)((const long long*)ei + N_EDGES))[e2];
        atomicAdd(&g_cnt[(int)d.x], 1);
        atomicAdd(&g_cnt[(int)d.y], 1);
    } else {
        int2 d = ((const int2*)((const int*)ei + N_EDGES))[e2];
        atomicAdd(&g_cnt[d.x], 1);
        atomicAdd(&g_cnt[d.y], 1);
    }
}

__global__ void scan_partial_kernel() {
    __shared__ int wsum[32];
    int tid = threadIdx.x;
    int lane = tid & 31, warp = tid >> 5;
    int i = blockIdx.x * SCAN_B + tid;
    int v = (i < N_NODES) ? g_cnt[i] : 0;
    int incl = v;
#pragma unroll
    for (int o = 1; o < 32; o <<= 1) {
        int t = __shfl_up_sync(0xffffffffu, incl, o);
        if (lane >= o) incl += t;
    }
    if (lane == 31) wsum[warp] = incl;
    __syncthreads();
    if (warp == 0) {
        int w = wsum[lane];
        int wincl = w;
#pragma unroll
        for (int o = 1; o < 32; o <<= 1) {
            int t = __shfl_up_sync(0xffffffffu, wincl, o);
            if (lane >= o) wincl += t;
        }
        wsum[lane] = wincl - w;
        if (lane == 31) g_bsum[blockIdx.x] = wincl;
    }
    __syncthreads();
    if (i < N_NODES) g_offp[i] = incl - v + wsum[warp];
}

__global__ void scan_bsum_kernel() {
    __shared__ int s[N_SBLK];
    int tid = threadIdx.x;
    if (tid < N_SBLK) s[tid] = g_bsum[tid];
    __syncthreads();
    if (tid == 0) {
        int run = 0;
        for (int b = 0; b < N_SBLK; b++) { int t = s[b]; s[b] = run; run += t; }
        g_off[N_NODES] = run;
    }
    __syncthreads();
    if (tid < N_SBLK) g_boff[tid] = s[tid];
}

__global__ void cursor_inv_kernel() {
    int i = blockIdx.x * blockDim.x + threadIdx.x;
    if (i < N_NODES) {
        int off = g_offp[i] + g_boff[i >> 10];
        g_off[i] = off;
        g_cur[i] = off;
        int d = g_cnt[i];
        g_inv[i] = 1.0f / (float)(d > 1 ? d : 1);
    }
}

__global__ void scatter_kernel(const void* ei) {
    int e2 = blockIdx.x * blockDim.x + threadIdx.x;
    if (e2 >= N_EDGES / 2) return;
    if (g_is64) {
        longlong2 s = ((const longlong2*)ei)[e2];
        longlong2 d = ((const longlong2*)((const long long*)ei + N_EDGES))[e2];
        int p0 = atomicAdd(&g_cur[(int)d.x], 1);
        g_col[p0] = (int)s.x;
        int p1 = atomicAdd(&g_cur[(int)d.y], 1);
        g_col[p1] = (int)s.y;
    } else {
        int2 s = ((const int2*)ei)[e2];
        int2 d = ((const int2*)((const int*)ei + N_EDGES))[e2];
        int p0 = atomicAdd(&g_cur[d.x], 1);
        g_col[p0] = s.x;
        int p1 = atomicAdd(&g_cur[d.y], 1);
        g_col[p1] = s.y;
    }
}

// ---------------- aggregation 1: warp/node, 4 edges/iter (quarter-warps) ---
// quarter q = lane>>3 owns edge b+4i+q; lane&7 owns 4 channels (uint2 = 4 half).
__global__ void agg1_kernel() {
    int node = blockIdx.x * 8 + (threadIdx.x >> 5);
    if (node >= N_NODES) return;
    int lane = threadIdx.x & 31;
    int q = lane >> 3, p = lane & 7;
    int b = g_off[node], e = g_off[node + 1];
    const uint2* x8 = (const uint2*)g_xh2;      // 8B = 4 half channels
    float4 acc = make_float4(0.f, 0.f, 0.f, 0.f);
    for (int i = b + q; i < e; i += 4) {
        int s = g_col[i];
        uint2 raw = x8[s * 8 + p];              // 64B row across 8 lanes
        __half2 h0 = *(__half2*)&raw.x;
        __half2 h1 = *(__half2*)&raw.y;
        float2 f0 = __half22float2(h0), f1 = __half22float2(h1);
        acc.x += f0.x; acc.y += f0.y; acc.z += f1.x; acc.w += f1.y;
    }
#pragma unroll
    for (int off = 8; off <= 16; off <<= 1) {
        acc.x += __shfl_xor_sync(0xffffffffu, acc.x, off);
        acc.y += __shfl_xor_sync(0xffffffffu, acc.y, off);
        acc.z += __shfl_xor_sync(0xffffffffu, acc.z, off);
        acc.w += __shfl_xor_sync(0xffffffffu, acc.w, off);
    }
    if (lane < 8)
        *(float4*)&g_agg1[node * 32 + p * 4] = acc;
}

// ---------------- aggregation 2: mean of p rows (64B fp16), 4 edges/iter ---
__global__ void agg2p_kernel() {
    int node = blockIdx.x * 8 + (threadIdx.x >> 5);
    if (node >= N_NODES) return;
    int lane = threadIdx.x & 31;
    int q = lane >> 3, p = lane & 7;
    int b = g_off[node], e = g_off[node + 1];
    const uint2* p8 = (const uint2*)g_pf;       // 8B = 4 half channels
    float4 acc = make_float4(0.f, 0.f, 0.f, 0.f);
    for (int i = b + q; i < e; i += 4) {
        int s = g_col[i];
        uint2 raw = p8[s * 8 + p];
        __half2 h0 = *(__half2*)&raw.x;
        __half2 h1 = *(__half2*)&raw.y;
        float2 f0 = __half22float2(h0), f1 = __half22float2(h1);
        acc.x += f0.x; acc.y += f0.y; acc.z += f1.x; acc.w += f1.y;
    }
#pragma unroll
    for (int off = 8; off <= 16; off <<= 1) {
        acc.x += __shfl_xor_sync(0xffffffffu, acc.x, off);
        acc.y += __shfl_xor_sync(0xffffffffu, acc.y, off);
        acc.z += __shfl_xor_sync(0xffffffffu, acc.z, off);
        acc.w += __shfl_xor_sync(0xffffffffu, acc.w, off);
    }
    if (lane < 8) {
        float sc = g_inv[node];
        float4 o = make_float4(acc.x * sc, acc.y * sc, acc.z * sc, acc.w * sc);
        *(float4*)&g_aggp[node * 32 + p * 4] = o;
    }
}

// ---------------- layer1 GEMM: h = relu([agg1*inv | x] @ [W1l|W1r]^T + b1) -
__global__ void gemm1_mma(const float* __restrict__ b1) {
    __shared__ __half sA[64 * 72];
    __shared__ __half sB[128 * 72];
    int tid = threadIdx.x, lane = tid & 31, warp = tid >> 5;
    int node0 = blockIdx.x * 64;

    for (int idx = tid; idx < 1024; idx += 128) {
        int row = idx >> 3, c8 = (idx & 7) * 8;
        *(uint4*)&sB[row * 72 + c8] = *(const uint4*)&g_w1h[row * 64 + c8];
    }
    for (int idx = tid; idx < 512; idx += 128) {
        int row = idx >> 3, s4 = (idx & 7) * 4;
        int gn = node0 + row;
        float4 v = make_float4(0.f, 0.f, 0.f, 0.f);
        float sc = 0.f;
        if (gn < N_NODES) { v = *(const float4*)&g_agg1[gn * 32 + s4]; sc = g_inv[gn]; }
        __half2 h0 = __floats2half2_rn(v.x * sc, v.y * sc);
        __half2 h1 = __floats2half2_rn(v.z * sc, v.w * sc);
        uint2 pk;
        pk.x = *(unsigned*)&h0; pk.y = *(unsigned*)&h1;
        *(uint2*)&sA[row * 72 + s4] = pk;
    }
    for (int idx = tid; idx < 256; idx += 128) {
        int row = idx >> 2, qq = idx & 3;
        int gn = node0 + row;
        uint4 v = make_uint4(0u, 0u, 0u, 0u);
        if (gn < N_NODES) v = ((const uint4*)g_xh2)[gn * 4 + qq];
        *(uint4*)&sA[row * 72 + 32 + qq * 8] = v;
    }
    __syncthreads();

    float d[16][4];
#pragma unroll
    for (int t = 0; t < 16; t++)
        d[t][0] = d[t][1] = d[t][2] = d[t][3] = 0.f;

    int ar = (lane & 7) + ((lane >> 3) & 1) * 8;
    int ac = (lane >> 4) * 8;
    int br = lane & 7;
    int bc = ((lane >> 3) & 1) * 8;

#pragma unroll
    for (int ks = 0; ks < 4; ks++) {
        int k0 = ks * 16;
        unsigned a0, a1, a2, a3;
        unsigned addrA = smem_u32(&sA[(warp * 16 + ar) * 72 + k0 + ac]);
        LDMATRIX_X4(a0, a1, a2, a3, addrA);
#pragma unroll
        for (int t = 0; t < 16; t++) {
            unsigned b0, b1r;
            unsigned addrB = smem_u32(&sB[(t * 8 + br) * 72 + k0 + bc]);
            LDMATRIX_X2(b0, b1r, addrB);
            MMA16816(d[t], a0, a1, a2, a3, b0, b1r);
        }
    }

    int g = lane >> 2, tg = lane & 3;
    int nA = node0 + warp * 16 + g;
    int nB = nA + 8;
#pragma unroll
    for (int t = 0; t < 16; t++) {
        int col = t * 8 + tg * 2;
        float bx = b1[col], by = b1[col + 1];
        if (nA < N_NODES) {
            __half2 h = __floats2half2_rn(fmaxf(d[t][0] + bx, 0.f),
                                          fmaxf(d[t][1] + by, 0.f));
            *(__half2*)&g_hf[nA * 128 + col] = h;
        }
        if (nB < N_NODES) {
            __half2 h = __floats2half2_rn(fmaxf(d[t][2] + bx, 0.f),
                                          fmaxf(d[t][3] + by, 0.f));
            *(__half2*)&g_hf[nB * 128 + col] = h;
        }
    }
}

// ---------------- gemm_p: p = h @ W2l^T (fp16 out, no bias) ----------------
// tile 128 nodes x 32 outs, 4 warps, K=128 in 2 chunks of 64.
__global__ void gemm_p_mma() {
    __shared__ __half sA[128 * 72];
    __shared__ __half sB[32 * 136];
    int tid = threadIdx.x, lane = tid & 31, warp = tid >> 5;
    int node0 = blockIdx.x * 128;

    for (int idx = tid; idx < 512; idx += 128) {   // 32x128 halves
        int row = idx >> 4, c8 = (idx & 15) * 8;
        *(uint4*)&sB[row * 136 + c8] = *(const uint4*)&g_w2h[row * 256 + c8];
    }

    float d[8][4];
#pragma unroll
    for (int t = 0; t < 8; t++)
        d[t][0] = d[t][1] = d[t][2] = d[t][3] = 0.f;

    int ar = (lane & 7) + ((lane >> 3) & 1) * 8;
    int ac = (lane >> 4) * 8;
    int br = lane & 7;
    int bc = ((lane >> 3) & 1) * 8;

    for (int chunk = 0; chunk < 2; chunk++) {
        if (chunk) __syncthreads();
        for (int idx = tid; idx < 1024; idx += 128) {
            int row = idx >> 3, qq = idx & 7;
            int gn = node0 + row;
            uint4 v = make_uint4(0u, 0u, 0u, 0u);
            if (gn < N_NODES) v = ((const uint4*)g_hf)[gn * 16 + chunk * 8 + qq];
            *(uint4*)&sA[row * 72 + qq * 8] = v;
        }
        __syncthreads();
#pragma unroll
        for (int ks = 0; ks < 4; ks++) {
            int k0 = ks * 16;
            unsigned bf[4][2];
#pragma unroll
            for (int nt = 0; nt < 4; nt++) {
                unsigned addrB = smem_u32(&sB[(nt * 8 + br) * 136 + chunk * 64 + k0 + bc]);
                LDMATRIX_X2(bf[nt][0], bf[nt][1], addrB);
            }
#pragma unroll
            for (int mt = 0; mt < 2; mt++) {
                unsigned a0, a1, a2, a3;
                unsigned addrA = smem_u32(&sA[(warp * 32 + mt * 16 + ar) * 72 + k0 + ac]);
                LDMATRIX_X4(a0, a1, a2, a3, addrA);
#pragma unroll
                for (int nt = 0; nt < 4; nt++)
                    MMA16816(d[mt * 4 + nt], a0, a1, a2, a3, bf[nt][0], bf[nt][1]);
            }
        }
    }

    int g = lane >> 2, tg = lane & 3;
#pragma unroll
    for (int mt = 0; mt < 2; mt++) {
        int nA = node0 + warp * 32 + mt * 16 + g;
        int nB = nA + 8;
#pragma unroll
        for (int nt = 0; nt < 4; nt++) {
            int col = nt * 8 + tg * 2;
            float* dd = d[mt * 4 + nt];
            if (nA < N_NODES) {
                __half2 h = __floats2half2_rn(dd[0], dd[1]);
                *(__half2*)&g_pf[nA * 32 + col] = h;
            }
            if (nB < N_NODES) {
                __half2 h = __floats2half2_rn(dd[2], dd[3]);
                *(__half2*)&g_pf[nB * 32 + col] = h;
            }
        }
    }
}

// ---------------- gemm_r: out = h @ W2r^T + b2 + mean_agg(p) ---------------
__global__ void gemm_r_mma(const float* __restrict__ b2, float* __restrict__ out) {
    __shared__ __half sA[128 * 72];
    __shared__ __half sB[32 * 136];
    int tid = threadIdx.x, lane = tid & 31, warp = tid >> 5;
    int node0 = blockIdx.x * 128;

    for (int idx = tid; idx < 512; idx += 128) {   // W2r half of g_w2h
        int row = idx >> 4, c8 = (idx & 15) * 8;
        *(uint4*)&sB[row * 136 + c8] = *(const uint4*)&g_w2h[row * 256 + 128 + c8];
    }

    float d[8][4];
#pragma unroll
    for (int t = 0; t < 8; t++)
        d[t][0] = d[t][1] = d[t][2] = d[t][3] = 0.f;

    int ar = (lane & 7) + ((lane >> 3) & 1) * 8;
    int ac = (lane >> 4) * 8;
    int br = lane & 7;
    int bc = ((lane >> 3) & 1) * 8;

    for (int chunk = 0; chunk < 2; chunk++) {
        if (chunk) __syncthreads();
        for (int idx = tid; idx < 1024; idx += 128) {
            int row = idx >> 3, qq = idx & 7;
            int gn = node0 + row;
            uint4 v = make_uint4(0u, 0u, 0u, 0u);
            if (gn < N_NODES) v = ((const uint4*)g_hf)[gn * 16 + chunk * 8 + qq];
            *(uint4*)&sA[row * 72 + qq * 8] = v;
        }
        __syncthreads();
#pragma unroll
        for (int ks = 0; ks < 4; ks++) {
            int k0 = ks * 16;
            unsigned bf[4][2];
#pragma unroll
            for (int nt = 0; nt < 4; nt++) {
                unsigned addrB = smem_u32(&sB[(nt * 8 + br) * 136 + chunk * 64 + k0 + bc]);
                LDMATRIX_X2(bf[nt][0], bf[nt][1], addrB);
            }
#pragma unroll
            for (int mt = 0; mt < 2; mt++) {
                unsigned a0, a1, a2, a3;
                unsigned addrA = smem_u32(&sA[(warp * 32 + mt * 16 + ar) * 72 + k0 + ac]);
                LDMATRIX_X4(a0, a1, a2, a3, addrA);
#pragma unroll
                for (int nt = 0; nt < 4; nt++)
                    MMA16816(d[mt * 4 + nt], a0, a1, a2, a3, bf[nt][0], bf[nt][1]);
            }
        }
    }

    int g = lane >> 2, tg = lane & 3;
#pragma unroll
    for (int mt = 0; mt < 2; mt++) {
        int nA = node0 + warp * 32 + mt * 16 + g;
        int nB = nA + 8;
#pragma unroll
        for (int nt = 0; nt < 4; nt++) {
            int col = nt * 8 + tg * 2;
            float bx = b2[col], by = b2[col + 1];
            float* dd = d[mt * 4 + nt];
            if (nA < N_NODES) {
                float2 m = *(const float2*)&g_aggp[nA * 32 + col];
                float2 o = make_float2(dd[0] + bx + m.x, dd[1] + by + m.y);
                *(float2*)&out[nA * 32 + col] = o;
            }
            if (nB < N_NODES) {
                float2 m = *(const float2*)&g_aggp[nB * 32 + col];
                float2 o = make_float2(dd[2] + bx + m.x, dd[3] + by + m.y);
                *(float2*)&out[nB * 32 + col] = o;
            }
        }
    }
}

// ---------------- launch ---------------------------------------------------
extern "C" void kernel_launch(void* const* d_in, const int* in_sizes, int n_in,
                              void* d_out, int out_size) {
    const float* x   = (const float*)d_in[0];
    const void*  ei  = d_in[1];
    const float* W1l = (const float*)d_in[2];
    const float* W1r = (const float*)d_in[3];
    const float* b1  = (const float*)d_in[4];
    const float* W2l = (const float*)d_in[5];
    const float* W2r = (const float*)d_in[6];
    const float* b2  = (const float*)d_in[7];
    float* out = (float*)d_out;

    const int TB = 256;
    int nb_nodes = (N_NODES + TB - 1) / TB;           // 391
    int nb_e2 = (N_EDGES / 2 + TB - 1) / TB;          // 3125

    prep_kernel<<<PB_TOT, TB>>>(x, W1l, W1r, W2l, W2r, (const unsigned int*)ei);
    hist_kernel<<<nb_e2, TB>>>(ei);
    scan_partial_kernel<<<N_SBLK, SCAN_B>>>();
    scan_bsum_kernel<<<1, 128>>>();
    cursor_inv_kernel<<<nb_nodes, TB>>>();
    scatter_kernel<<<nb_e2, TB>>>(ei);

    agg1_kernel<<<(N_NODES + 7) / 8, TB>>>();
    gemm1_mma<<<(N_NODES + 63) / 64, 128>>>(b1);
    gemm_p_mma<<<(N_NODES + 127) / 128, 128>>>();
    agg2p_kernel<<<(N_NODES + 7) / 8, TB>>>();
    gemm_r_mma<<<(N_NODES + 127) / 128, 128>>>(b2, out);
}